// round 5
// baseline (speedup 1.0000x reference)
#include <cuda_runtime.h>
#include <cuda_bf16.h>
#include <math.h>
#include <stdint.h>

#define NUM_HEADS 16
#define DMODEL    1024
#define DK        64
#define BATCH     2
#define SEQ       2048
#define MROWS     (BATCH * SEQ)      // 4096
#define KDIM      1024

// ---------------- scratch (device globals; no allocation allowed) ----------
__device__ __align__(128) float g_QKV[3ull * BATCH * NUM_HEADS * SEQ * DK];

#define XSZ (MROWS * KDIM)          // 4194304 elems per input matrix
#define WSZ (DMODEL * KDIM)         // 1048576 elems per weight matrix
__device__ __align__(128) __nv_bfloat16 g_Xhi[3 * XSZ];
__device__ __align__(128) __nv_bfloat16 g_Xlo[3 * XSZ];
__device__ __align__(128) __nv_bfloat16 g_Whi[4 * WSZ];
__device__ __align__(128) __nv_bfloat16 g_Wlo[4 * WSZ];
__device__ __align__(128) __nv_bfloat16 g_Ohi[XSZ];
__device__ __align__(128) __nv_bfloat16 g_Olo[XSZ];

// ==========================================================================
// helpers (arch-agnostic PTX: valid on plain sm_103 target)
// ==========================================================================
__device__ __forceinline__ uint32_t smem_u32(const void* p) {
    uint32_t a;
    asm("{ .reg .u64 t; cvta.to.shared.u64 t, %1; cvt.u32.u64 %0, t; }"
        : "=r"(a) : "l"(p));
    return a;
}

__device__ __forceinline__ void ldsm4(uint32_t* r, uint32_t addr) {
    asm volatile("ldmatrix.sync.aligned.m8n8.x4.shared.b16 {%0,%1,%2,%3}, [%4];"
                 : "=r"(r[0]), "=r"(r[1]), "=r"(r[2]), "=r"(r[3])
                 : "r"(addr));
}

__device__ __forceinline__ void mma16816(float* c, const uint32_t* a,
                                         uint32_t b0, uint32_t b1) {
    asm volatile(
        "mma.sync.aligned.m16n8k16.row.col.f32.bf16.bf16.f32 "
        "{%0,%1,%2,%3}, {%4,%5,%6,%7}, {%8,%9}, {%0,%1,%2,%3};"
        : "+f"(c[0]), "+f"(c[1]), "+f"(c[2]), "+f"(c[3])
        : "r"(a[0]), "r"(a[1]), "r"(a[2]), "r"(a[3]), "r"(b0), "r"(b1));
}

__device__ __forceinline__ void cpasync16(uint32_t dst, const void* src) {
    asm volatile("cp.async.cg.shared.global [%0], [%1], 16;"
                 :: "r"(dst), "l"(src) : "memory");
}
__device__ __forceinline__ void cp_commit() {
    asm volatile("cp.async.commit_group;" ::: "memory");
}
template <int N>
__device__ __forceinline__ void cp_wait() {
    asm volatile("cp.async.wait_group %0;" :: "n"(N) : "memory");
}

__device__ __forceinline__ uint32_t packbf(__nv_bfloat16 a, __nv_bfloat16 b) {
    return (uint32_t)__bfloat16_as_ushort(a) |
           ((uint32_t)__bfloat16_as_ushort(b) << 16);
}

// fp32x4 -> hi bf16x4 (8B) + lo bf16x4 (8B)
__device__ __forceinline__ void cvt_split8(float4 v, char* hiP, char* loP) {
    __nv_bfloat16 h0 = __float2bfloat16(v.x);
    __nv_bfloat16 h1 = __float2bfloat16(v.y);
    __nv_bfloat16 h2 = __float2bfloat16(v.z);
    __nv_bfloat16 h3 = __float2bfloat16(v.w);
    __nv_bfloat16 l0 = __float2bfloat16(v.x - __bfloat162float(h0));
    __nv_bfloat16 l1 = __float2bfloat16(v.y - __bfloat162float(h1));
    __nv_bfloat16 l2 = __float2bfloat16(v.z - __bfloat162float(h2));
    __nv_bfloat16 l3 = __float2bfloat16(v.w - __bfloat162float(h3));
    *(uint2*)hiP = make_uint2(packbf(h0, h1), packbf(h2, h3));
    *(uint2*)loP = make_uint2(packbf(l0, l1), packbf(l2, l3));
}

// ==========================================================================
// pre-conversion: fp32 -> bf16 hi/lo, for 3 inputs (z<3) + 4 weights (z>=3)
// ==========================================================================
__global__ __launch_bounds__(256)
void cvt_kernel(const float* __restrict__ Qin, const float* __restrict__ Kin,
                const float* __restrict__ Vin,
                const float* __restrict__ Wq, const float* __restrict__ Wk,
                const float* __restrict__ Wv, const float* __restrict__ Wo)
{
    const int z = blockIdx.z;
    const float* src;
    __nv_bfloat16 *dhi, *dlo;
    size_t n4;
    if (z < 3) {
        src = (z == 0) ? Qin : (z == 1) ? Kin : Vin;
        dhi = g_Xhi + (size_t)z * XSZ;
        dlo = g_Xlo + (size_t)z * XSZ;
        n4  = XSZ / 4;
    } else {
        const int w = z - 3;
        src = (w == 0) ? Wq : (w == 1) ? Wk : (w == 2) ? Wv : Wo;
        dhi = g_Whi + (size_t)w * WSZ;
        dlo = g_Wlo + (size_t)w * WSZ;
        n4  = WSZ / 4;
    }
    const size_t stride = (size_t)gridDim.x * blockDim.x;
    for (size_t i = (size_t)blockIdx.x * blockDim.x + threadIdx.x; i < n4; i += stride) {
        float4 v = ((const float4*)src)[i];
        cvt_split8(v, (char*)(dhi + i * 4), (char*)(dlo + i * 4));
    }
}

// ==========================================================================
// bf16-input tensor-core GEMM, cp.async 3-stage pipeline.
// C = A @ B^T + bias (compensated: hh + hl + lh). A:[M,1024], B:[N,1024].
// BM=BN=128, BK=32, 256 thr (8 warps 2x4), smem 3 x 40960B.
// ==========================================================================
#define ST_STR   80
#define ST_TILE  (128 * ST_STR)     // 10240
#define ST_AHI   0
#define ST_ALO   ST_TILE
#define ST_BHI   (2 * ST_TILE)
#define ST_BLO   (3 * ST_TILE)
#define STAGE_SZ (4 * ST_TILE)      // 40960
#define NSTAGE   3
#define GSMEM2   (NSTAGE * STAGE_SZ) // 122880
#define KCHUNK   (KDIM / 32)        // 32

template <bool SPLIT>
__device__ __forceinline__ void gemm_bf16_body(const __nv_bfloat16* __restrict__ Ahi,
                                               const __nv_bfloat16* __restrict__ Alo,
                                               const __nv_bfloat16* __restrict__ Bhi,
                                               const __nv_bfloat16* __restrict__ Blo,
                                               const float* __restrict__ bias,
                                               float* __restrict__ C)
{
    extern __shared__ __align__(128) char smem2[];
    const uint32_t sbase = smem_u32(smem2);

    const int t   = threadIdx.x;
    const int l   = t & 31;
    const int wid = t >> 5;
    const int wm  = wid & 1;
    const int wn  = wid >> 1;
    const int rowBlk = blockIdx.y * 128;
    const int colBlk = blockIdx.x * 128;

    // cp.async mapping: thread -> rows (t>>2, +64), 16B granule (t&3)
    const int r0   = t >> 2;
    const int gb   = (t & 3) * 16;      // dst byte offset in row
    const int ke   = (t & 3) * 8;       // src element offset in 32-elem chunk
    const __nv_bfloat16* Ah0 = Ahi + (size_t)(rowBlk + r0) * KDIM + ke;
    const __nv_bfloat16* Al0 = Alo + (size_t)(rowBlk + r0) * KDIM + ke;
    const __nv_bfloat16* Bh0 = Bhi + (size_t)(colBlk + r0) * KDIM + ke;
    const __nv_bfloat16* Bl0 = Blo + (size_t)(colBlk + r0) * KDIM + ke;

    auto issue = [&](int c) {
        if (c < KCHUNK) {
            const uint32_t sb = sbase + (uint32_t)(c % NSTAGE) * STAGE_SZ;
            const int ko = c * 32;
#pragma unroll
            for (int rr = 0; rr < 2; rr++) {
                const uint32_t d = (uint32_t)(r0 + rr * 64) * ST_STR + gb;
                const size_t so = (size_t)(rr * 64) * KDIM + ko;
                cpasync16(sb + ST_AHI + d, Ah0 + so);
                cpasync16(sb + ST_ALO + d, Al0 + so);
                cpasync16(sb + ST_BHI + d, Bh0 + so);
                cpasync16(sb + ST_BLO + d, Bl0 + so);
            }
        }
        cp_commit();
    };

    float acc[4][4][4];
#pragma unroll
    for (int mi = 0; mi < 4; mi++)
#pragma unroll
        for (int ni = 0; ni < 4; ni++)
#pragma unroll
            for (int k = 0; k < 4; k++) acc[mi][ni][k] = 0.f;

    const uint32_t lr  = (uint32_t)(l & 15);
    const uint32_t lcb = (uint32_t)(l >> 4) * 16;
    const uint32_t aOff = (uint32_t)(wm * 64 + lr) * ST_STR + lcb;
    const uint32_t bOff = (uint32_t)(wn * 32 + lr) * ST_STR + lcb;

    issue(0);
    issue(1);

    for (int c = 0; c < KCHUNK; c++) {
        cp_wait<1>();
        __syncthreads();
        issue(c + 2);

        const uint32_t sb   = sbase + (uint32_t)(c % NSTAGE) * STAGE_SZ;
        const uint32_t aBase = sb + ST_AHI + aOff;
        const uint32_t bBase = sb + ST_BHI + bOff;

#pragma unroll
        for (int ks = 0; ks < 2; ks++) {
            const uint32_t ko = (uint32_t)ks * 32;
            uint32_t ah[4][4], al[4][4];
#pragma unroll
            for (int mi = 0; mi < 4; mi++) {
                ldsm4(ah[mi], aBase + mi * (16 * ST_STR) + ko);
                ldsm4(al[mi], aBase + ST_TILE + mi * (16 * ST_STR) + ko);
            }
            uint32_t bh[2][4], bl[2][4];
#pragma unroll
            for (int g = 0; g < 2; g++) {
                ldsm4(bh[g], bBase + g * (16 * ST_STR) + ko);
                ldsm4(bl[g], bBase + ST_TILE + g * (16 * ST_STR) + ko);
            }
#pragma unroll
            for (int mi = 0; mi < 4; mi++) {
#pragma unroll
                for (int ni = 0; ni < 4; ni++) {
                    const int g = ni >> 1, s = ni & 1;
                    mma16816(acc[mi][ni], ah[mi], bh[g][s], bh[g][s + 2]);
                    mma16816(acc[mi][ni], ah[mi], bl[g][s], bl[g][s + 2]);
                    mma16816(acc[mi][ni], al[mi], bh[g][s], bh[g][s + 2]);
                }
            }
        }
    }

    // ---- epilogue: bias + store ----
#pragma unroll
    for (int mi = 0; mi < 4; mi++) {
        const int rBase = rowBlk + wm * 64 + mi * 16 + (l >> 2);
#pragma unroll
        for (int ni = 0; ni < 4; ni++) {
            const int n = colBlk + wn * 32 + ni * 8 + (l & 3) * 2;
            const float2 bb = *(const float2*)(bias + n);
#pragma unroll
            for (int h2 = 0; h2 < 2; h2++) {
                const int m = rBase + h2 * 8;
                float2 v;
                v.x = acc[mi][ni][h2 * 2 + 0] + bb.x;
                v.y = acc[mi][ni][h2 * 2 + 1] + bb.y;
                if (SPLIT) {
                    const int b = m >> 11;
                    const int s = m & (SEQ - 1);
                    const int h = n >> 6;
                    const int d = n & (DK - 1);
                    *(float2*)&C[(((size_t)(b * NUM_HEADS + h) * SEQ + s) * DK) + d] = v;
                } else {
                    *(float2*)&C[(size_t)m * DMODEL + n] = v;
                }
            }
        }
    }
}

__global__ __launch_bounds__(256, 1)
void qkv_tc_kernel(const float* __restrict__ bq,
                   const float* __restrict__ bk,
                   const float* __restrict__ bv)
{
    const int z = blockIdx.z;
    const float* bias = (z == 0) ? bq : (z == 1) ? bk : bv;
    gemm_bf16_body<true>(g_Xhi + (size_t)z * XSZ, g_Xlo + (size_t)z * XSZ,
                         g_Whi + (size_t)z * WSZ, g_Wlo + (size_t)z * WSZ,
                         bias, g_QKV + (size_t)z * BATCH * NUM_HEADS * SEQ * DK);
}

__global__ __launch_bounds__(256, 1)
void out_tc_kernel(const float* __restrict__ bo, float* __restrict__ out)
{
    gemm_bf16_body<false>(g_Ohi, g_Olo, g_Whi + 3ull * WSZ, g_Wlo + 3ull * WSZ,
                          bo, out);
}

// ==========================================================================
// Flash attention on tensor cores (bf16x3), unchanged except epilogue now
// writes bf16 hi/lo directly (identical rounding to previous fp32->split).
// ==========================================================================
#define FSTR   144
#define FT     (64 * FSTR)
#define F_KHI  0
#define F_KLO  FT
#define F_VHI  (2 * FT)
#define F_VLO  (3 * FT)
#define FSMEM  (4 * FT)

__global__ __launch_bounds__(256, 1)
void flash_tc_kernel()
{
    __shared__ __align__(128) char smem[FSMEM];
    const uint32_t sbase = smem_u32(smem);

    const int t  = threadIdx.x;
    const int l  = t & 31;
    const int w  = t >> 5;
    const int q0 = blockIdx.x * 128;
    const int h  = blockIdx.y;
    const int b  = blockIdx.z;

    const size_t headBase = ((size_t)b * NUM_HEADS + h) * SEQ * DK;
    const float* Qg = g_QKV + headBase;
    const float* Kg = g_QKV + 1ull * BATCH * NUM_HEADS * SEQ * DK + headBase;
    const float* Vg = g_QKV + 2ull * BATCH * NUM_HEADS * SEQ * DK + headBase;

    const float SCALE = 0.125f;

    {
        const int row  = t >> 1;
        const int half = (t & 1) * 32;
#pragma unroll
        for (int i = 0; i < 8; i++) {
            float4 q = *(const float4*)&Qg[(size_t)(q0 + row) * DK + half + 4 * i];
            q.x *= SCALE; q.y *= SCALE; q.z *= SCALE; q.w *= SCALE;
            const uint32_t o = (uint32_t)row * FSTR + (uint32_t)(half + 4 * i) * 2;
            cvt_split8(q, smem + o, smem + 2 * FT + o);
        }
    }
    __syncthreads();

    uint32_t qh[4][4], ql[4][4];
    {
        const uint32_t aBase = sbase + (uint32_t)(w * 16 + (l & 15)) * FSTR
                             + (uint32_t)(l >> 4) * 16;
#pragma unroll
        for (int kt = 0; kt < 4; kt++) {
            ldsm4(qh[kt], aBase + kt * 32);
            ldsm4(ql[kt], aBase + 2 * FT + kt * 32);
        }
    }
    __syncthreads();

    float o_[8][4];
#pragma unroll
    for (int j = 0; j < 8; j++)
#pragma unroll
        for (int k = 0; k < 4; k++) o_[j][k] = 0.f;
    float m0 = -1e30f, m1 = -1e30f, l0 = 0.f, l1 = 0.f;

    const uint32_t lbase = sbase + (uint32_t)(l & 15) * FSTR + (uint32_t)(l >> 4) * 16;

    for (int j0 = 0; j0 < SEQ; j0 += 64) {
        {
            const int key  = t >> 2;
            const int doff = (t & 3) * 16;
#pragma unroll
            for (int i = 0; i < 4; i++) {
                float4 kv = *(const float4*)&Kg[(size_t)(j0 + key) * DK + doff + 4 * i];
                const uint32_t o = (uint32_t)key * FSTR + (uint32_t)(doff + 4 * i) * 2;
                cvt_split8(kv, smem + F_KHI + o, smem + F_KLO + o);
            }
#pragma unroll
            for (int i = 0; i < 4; i++) {
                float4 vv = *(const float4*)&Vg[(size_t)(j0 + key) * DK + doff + 4 * i];
                const float vf[4] = {vv.x, vv.y, vv.z, vv.w};
#pragma unroll
                for (int c2 = 0; c2 < 4; c2++) {
                    const int d = doff + 4 * i + c2;
                    __nv_bfloat16 hi = __float2bfloat16(vf[c2]);
                    __nv_bfloat16 lo = __float2bfloat16(vf[c2] - __bfloat162float(hi));
                    const uint32_t o = (uint32_t)d * FSTR + (uint32_t)key * 2;
                    *(__nv_bfloat16*)(smem + F_VHI + o) = hi;
                    *(__nv_bfloat16*)(smem + F_VLO + o) = lo;
                }
            }
        }
        __syncthreads();

        float s[8][4];
#pragma unroll
        for (int j = 0; j < 8; j++)
#pragma unroll
            for (int k = 0; k < 4; k++) s[j][k] = 0.f;

#pragma unroll
        for (int kt = 0; kt < 4; kt++) {
#pragma unroll
            for (int kg = 0; kg < 4; kg++) {
                uint32_t kh[4], kl[4];
                ldsm4(kh, lbase + F_KHI + kg * (16 * FSTR) + kt * 32);
                ldsm4(kl, lbase + F_KLO + kg * (16 * FSTR) + kt * 32);
#pragma unroll
                for (int ss = 0; ss < 2; ss++) {
                    float* sc = s[2 * kg + ss];
                    mma16816(sc, qh[kt], kh[ss], kh[ss + 2]);
                    mma16816(sc, qh[kt], kl[ss], kl[ss + 2]);
                    mma16816(sc, ql[kt], kh[ss], kh[ss + 2]);
                }
            }
        }

        {
            float mx0 = s[0][0], mx1 = s[0][2];
#pragma unroll
            for (int j = 0; j < 8; j++) {
                mx0 = fmaxf(mx0, fmaxf(s[j][0], s[j][1]));
                mx1 = fmaxf(mx1, fmaxf(s[j][2], s[j][3]));
            }
            mx0 = fmaxf(mx0, __shfl_xor_sync(0xffffffffu, mx0, 1));
            mx0 = fmaxf(mx0, __shfl_xor_sync(0xffffffffu, mx0, 2));
            mx1 = fmaxf(mx1, __shfl_xor_sync(0xffffffffu, mx1, 1));
            mx1 = fmaxf(mx1, __shfl_xor_sync(0xffffffffu, mx1, 2));

            const float mn0 = fmaxf(m0, mx0);
            const float mn1 = fmaxf(m1, mx1);
            const float c0 = __expf(m0 - mn0);
            const float c1 = __expf(m1 - mn1);
            m0 = mn0; m1 = mn1;

            float rs0 = 0.f, rs1 = 0.f;
#pragma unroll
            for (int j = 0; j < 8; j++) {
                s[j][0] = __expf(s[j][0] - mn0);
                s[j][1] = __expf(s[j][1] - mn0);
                s[j][2] = __expf(s[j][2] - mn1);
                s[j][3] = __expf(s[j][3] - mn1);
                rs0 += s[j][0] + s[j][1];
                rs1 += s[j][2] + s[j][3];
            }
            rs0 += __shfl_xor_sync(0xffffffffu, rs0, 1);
            rs0 += __shfl_xor_sync(0xffffffffu, rs0, 2);
            rs1 += __shfl_xor_sync(0xffffffffu, rs1, 1);
            rs1 += __shfl_xor_sync(0xffffffffu, rs1, 2);
            l0 = l0 * c0 + rs0;
            l1 = l1 * c1 + rs1;

#pragma unroll
            for (int j = 0; j < 8; j++) {
                o_[j][0] *= c0; o_[j][1] *= c0;
                o_[j][2] *= c1; o_[j][3] *= c1;
            }
        }

#pragma unroll
        for (int kt = 0; kt < 4; kt++) {
            uint32_t phi[4], plo[4];
#pragma unroll
            for (int half = 0; half < 2; half++) {
                const float* sp = s[2 * kt + half];
#pragma unroll
                for (int rr = 0; rr < 2; rr++) {
                    const float x = sp[2 * rr + 0], y = sp[2 * rr + 1];
                    __nv_bfloat16 hx = __float2bfloat16(x);
                    __nv_bfloat16 hy = __float2bfloat16(y);
                    __nv_bfloat16 lx = __float2bfloat16(x - __bfloat162float(hx));
                    __nv_bfloat16 ly = __float2bfloat16(y - __bfloat162float(hy));
                    phi[2 * half + rr] = packbf(hx, hy);
                    plo[2 * half + rr] = packbf(lx, ly);
                }
            }
#pragma unroll
            for (int dg = 0; dg < 4; dg++) {
                uint32_t vh[4], vl[4];
                ldsm4(vh, lbase + F_VHI + dg * (16 * FSTR) + kt * 32);
                ldsm4(vl, lbase + F_VLO + dg * (16 * FSTR) + kt * 32);
#pragma unroll
                for (int ss = 0; ss < 2; ss++) {
                    float* oc = o_[2 * dg + ss];
                    mma16816(oc, phi, vh[ss], vh[ss + 2]);
                    mma16816(oc, phi, vl[ss], vl[ss + 2]);
                    mma16816(oc, plo, vh[ss], vh[ss + 2]);
                }
            }
        }
        __syncthreads();
    }

    // ---- epilogue: normalize, write bf16 hi/lo merged-head [b*S, DMODEL] ----
    {
        const float inv0 = 1.f / l0;
        const float inv1 = 1.f / l1;
        const int r0 = q0 + w * 16 + (l >> 2);
        const int r1 = r0 + 8;
        const size_t ro0 = ((size_t)b * SEQ + r0) * DMODEL;
        const size_t ro1 = ((size_t)b * SEQ + r1) * DMODEL;
#pragma unroll
        for (int j = 0; j < 8; j++) {
            const int d = h * DK + j * 8 + (l & 3) * 2;
            {
                const float x = o_[j][0] * inv0, y = o_[j][1] * inv0;
                __nv_bfloat16 hx = __float2bfloat16(x), hy = __float2bfloat16(y);
                __nv_bfloat16 lx = __float2bfloat16(x - __bfloat162float(hx));
                __nv_bfloat16 ly = __float2bfloat16(y - __bfloat162float(hy));
                *(uint32_t*)&g_Ohi[ro0 + d] = packbf(hx, hy);
                *(uint32_t*)&g_Olo[ro0 + d] = packbf(lx, ly);
            }
            {
                const float x = o_[j][2] * inv1, y = o_[j][3] * inv1;
                __nv_bfloat16 hx = __float2bfloat16(x), hy = __float2bfloat16(y);
                __nv_bfloat16 lx = __float2bfloat16(x - __bfloat162float(hx));
                __nv_bfloat16 ly = __float2bfloat16(y - __bfloat162float(hy));
                *(uint32_t*)&g_Ohi[ro1 + d] = packbf(hx, hy);
                *(uint32_t*)&g_Olo[ro1 + d] = packbf(lx, ly);
            }
        }
    }
}

// ==========================================================================
// launch
// ==========================================================================
extern "C" void kernel_launch(void* const* d_in, const int* in_sizes, int n_in,
                              void* d_out, int out_size)
{
    (void)in_sizes; (void)n_in; (void)out_size;
    const float* Qin = (const float*)d_in[0];
    const float* Kin = (const float*)d_in[1];
    const float* Vin = (const float*)d_in[2];
    const float* Wq  = (const float*)d_in[3];
    const float* bq  = (const float*)d_in[4];
    const float* Wk  = (const float*)d_in[5];
    const float* bk  = (const float*)d_in[6];
    const float* Wv  = (const float*)d_in[7];
    const float* bv  = (const float*)d_in[8];
    const float* Wo  = (const float*)d_in[9];
    const float* bo  = (const float*)d_in[10];
    float* out = (float*)d_out;

    cudaFuncSetAttribute(qkv_tc_kernel,
                         cudaFuncAttributeMaxDynamicSharedMemorySize, GSMEM2);
    cudaFuncSetAttribute(out_tc_kernel,
                         cudaFuncAttributeMaxDynamicSharedMemorySize, GSMEM2);

    dim3 gCvt(1024, 1, 7);
    cvt_kernel<<<gCvt, 256>>>(Qin, Kin, Vin, Wq, Wk, Wv, Wo);

    dim3 gProj(DMODEL / 128, MROWS / 128, 3);
    qkv_tc_kernel<<<gProj, 256, GSMEM2>>>(bq, bk, bv);

    dim3 gAttn(SEQ / 128, NUM_HEADS, BATCH);
    flash_tc_kernel<<<gAttn, 256>>>();

    dim3 gOut(DMODEL / 128, MROWS / 128, 1);
    out_tc_kernel<<<gOut, 256, GSMEM2>>>(bo, out);
}

// round 7
// speedup vs baseline: 1.5927x; 1.5927x over previous
#include <cuda_runtime.h>
#include <cuda_bf16.h>
#include <math.h>
#include <stdint.h>

#define NUM_HEADS 16
#define DMODEL    1024
#define DK        64
#define BATCH     2
#define SEQ       2048
#define MROWS     (BATCH * SEQ)      // 4096
#define KDIM      1024
#define HSZ       (BATCH * NUM_HEADS * SEQ * DK)   // 4194304

// ---------------- scratch (device globals; no allocation allowed) ----------
__device__ __align__(128) float g_Q[HSZ];                 // fp32 Q [b,h,s,d]
__device__ __align__(128) __nv_bfloat16 g_Khi[HSZ];
__device__ __align__(128) __nv_bfloat16 g_Klo[HSZ];
__device__ __align__(128) __nv_bfloat16 g_Vhi[HSZ];
__device__ __align__(128) __nv_bfloat16 g_Vlo[HSZ];
__device__ __align__(128) float g_O[(size_t)MROWS * DMODEL];

// ==========================================================================
// warp-MMA helpers (arch-agnostic PTX: valid on plain sm_103 target)
// ==========================================================================
__device__ __forceinline__ uint32_t smem_u32(const void* p) {
    uint32_t a;
    asm("{ .reg .u64 t; cvta.to.shared.u64 t, %1; cvt.u32.u64 %0, t; }"
        : "=r"(a) : "l"(p));
    return a;
}

__device__ __forceinline__ void ldsm4(uint32_t* r, uint32_t addr) {
    asm volatile("ldmatrix.sync.aligned.m8n8.x4.shared.b16 {%0,%1,%2,%3}, [%4];"
                 : "=r"(r[0]), "=r"(r[1]), "=r"(r[2]), "=r"(r[3])
                 : "r"(addr));
}

__device__ __forceinline__ void ldsm4t(uint32_t* r, uint32_t addr) {
    asm volatile("ldmatrix.sync.aligned.m8n8.x4.trans.shared.b16 {%0,%1,%2,%3}, [%4];"
                 : "=r"(r[0]), "=r"(r[1]), "=r"(r[2]), "=r"(r[3])
                 : "r"(addr));
}

__device__ __forceinline__ void mma16816(float* c, const uint32_t* a,
                                         uint32_t b0, uint32_t b1) {
    asm volatile(
        "mma.sync.aligned.m16n8k16.row.col.f32.bf16.bf16.f32 "
        "{%0,%1,%2,%3}, {%4,%5,%6,%7}, {%8,%9}, {%0,%1,%2,%3};"
        : "+f"(c[0]), "+f"(c[1]), "+f"(c[2]), "+f"(c[3])
        : "r"(a[0]), "r"(a[1]), "r"(a[2]), "r"(a[3]), "r"(b0), "r"(b1));
}

__device__ __forceinline__ uint32_t packbf(__nv_bfloat16 a, __nv_bfloat16 b) {
    return (uint32_t)__bfloat16_as_ushort(a) |
           ((uint32_t)__bfloat16_as_ushort(b) << 16);
}

// fp32x4 -> hi bf16x4 (8B) + lo bf16x4 (8B)
__device__ __forceinline__ void cvt_split8b(float4 v, char* hiP, char* loP) {
    __nv_bfloat16 h0 = __float2bfloat16(v.x);
    __nv_bfloat16 h1 = __float2bfloat16(v.y);
    __nv_bfloat16 h2 = __float2bfloat16(v.z);
    __nv_bfloat16 h3 = __float2bfloat16(v.w);
    __nv_bfloat16 l0 = __float2bfloat16(v.x - __bfloat162float(h0));
    __nv_bfloat16 l1 = __float2bfloat16(v.y - __bfloat162float(h1));
    __nv_bfloat16 l2 = __float2bfloat16(v.z - __bfloat162float(h2));
    __nv_bfloat16 l3 = __float2bfloat16(v.w - __bfloat162float(h3));
    *(uint2*)hiP = make_uint2(packbf(h0, h1), packbf(h2, h3));
    *(uint2*)loP = make_uint2(packbf(l0, l1), packbf(l2, l3));
}

// ==========================================================================
// Tensor-core GEMM (HMMA), R4 structure: fp32 loads + in-loop hi/lo split,
// register prefetch, single 40KB stage. Epilogue modes:
//   SPLIT=0: C fp32 row-major [M, DMODEL]
//   SPLIT=1: [b,h,s,d] layout; fp32 (Q) if Chi==null, else bf16 hi/lo (K,V)
// ==========================================================================
#define TSTRIDE 80
#define TILESZ  (128 * TSTRIDE)
#define S_AHI   0
#define S_ALO   TILESZ
#define S_BHI   (2 * TILESZ)
#define S_BLO   (3 * TILESZ)
#define GSMEM   (4 * TILESZ)
#define KCHUNK  32

template <bool SPLIT>
__device__ __forceinline__ void gemm_tc_body(const float* __restrict__ A,
                                             const float* __restrict__ W,
                                             const float* __restrict__ bias,
                                             float* __restrict__ Cf,
                                             __nv_bfloat16* __restrict__ Chi,
                                             __nv_bfloat16* __restrict__ Clo)
{
    __shared__ __align__(128) char smem[GSMEM];
    const uint32_t sbase = smem_u32(smem);

    const int t   = threadIdx.x;
    const int l   = t & 31;
    const int wid = t >> 5;
    const int wm  = wid & 1;
    const int wn  = wid >> 1;
    const int rowBlk = blockIdx.y * 128;
    const int colBlk = blockIdx.x * 128;

    const int lrow = t >> 3;
    const int col4 = (t & 7) * 4;
    const float* Ap = A + (size_t)(rowBlk + lrow) * KDIM + col4;
    const float* Wp = W + (size_t)(colBlk + lrow) * KDIM + col4;
    const uint32_t stoff = (uint32_t)lrow * TSTRIDE + (uint32_t)col4 * 2;

    float acc[4][4][4];
#pragma unroll
    for (int mi = 0; mi < 4; mi++)
#pragma unroll
        for (int ni = 0; ni < 4; ni++)
#pragma unroll
            for (int k = 0; k < 4; k++) acc[mi][ni][k] = 0.f;

    const uint32_t lr  = (uint32_t)(l & 15);
    const uint32_t lcb = (uint32_t)(l >> 4) * 16;
    const uint32_t aBase = sbase + S_AHI + (wm * 64 + lr) * TSTRIDE + lcb;
    const uint32_t bBase = sbase + S_BHI + (wn * 32 + lr) * TSTRIDE + lcb;

    float4 pfA[4], pfB[4];
#pragma unroll
    for (int i = 0; i < 4; i++) {
        pfA[i] = *(const float4*)(Ap + (size_t)(i * 32) * KDIM);
        pfB[i] = *(const float4*)(Wp + (size_t)(i * 32) * KDIM);
    }

    for (int c = 0; c < KCHUNK; c++) {
#pragma unroll
        for (int i = 0; i < 4; i++) {
            const uint32_t o = stoff + (uint32_t)i * (32 * TSTRIDE);
            cvt_split8b(pfA[i], smem + S_AHI + o, smem + S_ALO + o);
            cvt_split8b(pfB[i], smem + S_BHI + o, smem + S_BLO + o);
        }
        __syncthreads();

        if (c + 1 < KCHUNK) {
            const int ko = (c + 1) * 32;
#pragma unroll
            for (int i = 0; i < 4; i++) {
                pfA[i] = *(const float4*)(Ap + (size_t)(i * 32) * KDIM + ko);
                pfB[i] = *(const float4*)(Wp + (size_t)(i * 32) * KDIM + ko);
            }
        }

#pragma unroll
        for (int ks = 0; ks < 2; ks++) {
            const uint32_t ko = (uint32_t)ks * 32;
            uint32_t ah[4][4], al[4][4];
#pragma unroll
            for (int mi = 0; mi < 4; mi++) {
                ldsm4(ah[mi], aBase + mi * (16 * TSTRIDE) + ko);
                ldsm4(al[mi], aBase + TILESZ + mi * (16 * TSTRIDE) + ko);
            }
            uint32_t bh[2][4], bl[2][4];
#pragma unroll
            for (int g = 0; g < 2; g++) {
                ldsm4(bh[g], bBase + g * (16 * TSTRIDE) + ko);
                ldsm4(bl[g], bBase + TILESZ + g * (16 * TSTRIDE) + ko);
            }
#pragma unroll
            for (int mi = 0; mi < 4; mi++) {
#pragma unroll
                for (int ni = 0; ni < 4; ni++) {
                    const int g = ni >> 1, s = ni & 1;
                    mma16816(acc[mi][ni], ah[mi], bh[g][s], bh[g][s + 2]);
                    mma16816(acc[mi][ni], ah[mi], bl[g][s], bl[g][s + 2]);
                    mma16816(acc[mi][ni], al[mi], bh[g][s], bh[g][s + 2]);
                }
            }
        }
        __syncthreads();
    }

    // ---- epilogue: bias + store ----
#pragma unroll
    for (int mi = 0; mi < 4; mi++) {
        const int rBase = rowBlk + wm * 64 + mi * 16 + (l >> 2);
#pragma unroll
        for (int ni = 0; ni < 4; ni++) {
            const int n = colBlk + wn * 32 + ni * 8 + (l & 3) * 2;
            const float2 bb = *(const float2*)(bias + n);
#pragma unroll
            for (int h2 = 0; h2 < 2; h2++) {
                const int m = rBase + h2 * 8;
                float2 v;
                v.x = acc[mi][ni][h2 * 2 + 0] + bb.x;
                v.y = acc[mi][ni][h2 * 2 + 1] + bb.y;
                if (SPLIT) {
                    const int b = m >> 11;
                    const int s = m & (SEQ - 1);
                    const int h = n >> 6;
                    const int d = n & (DK - 1);
                    const size_t idx = (((size_t)(b * NUM_HEADS + h) * SEQ + s) * DK) + d;
                    if (Chi == nullptr) {
                        *(float2*)&Cf[idx] = v;
                    } else {
                        __nv_bfloat16 hx = __float2bfloat16(v.x);
                        __nv_bfloat16 hy = __float2bfloat16(v.y);
                        __nv_bfloat16 lx = __float2bfloat16(v.x - __bfloat162float(hx));
                        __nv_bfloat16 ly = __float2bfloat16(v.y - __bfloat162float(hy));
                        *(uint32_t*)&Chi[idx] = packbf(hx, hy);
                        *(uint32_t*)&Clo[idx] = packbf(lx, ly);
                    }
                } else {
                    *(float2*)&Cf[(size_t)m * DMODEL + n] = v;
                }
            }
        }
    }
}

__global__ __launch_bounds__(256, 1)
void qkv_tc_kernel(const float* __restrict__ Qin,
                   const float* __restrict__ Kin,
                   const float* __restrict__ Vin,
                   const float* __restrict__ Wq, const float* __restrict__ bq,
                   const float* __restrict__ Wk, const float* __restrict__ bk,
                   const float* __restrict__ Wv, const float* __restrict__ bv)
{
    const int z = blockIdx.z;
    if (z == 0) {
        gemm_tc_body<true>(Qin, Wq, bq, g_Q, nullptr, nullptr);
    } else if (z == 1) {
        gemm_tc_body<true>(Kin, Wk, bk, nullptr, g_Khi, g_Klo);
    } else {
        gemm_tc_body<true>(Vin, Wv, bv, nullptr, g_Vhi, g_Vlo);
    }
}

__global__ __launch_bounds__(256, 1)
void out_tc_kernel(const float* __restrict__ Wo,
                   const float* __restrict__ bo,
                   float* __restrict__ out)
{
    gemm_tc_body<false>(g_O, Wo, bo, out, nullptr, nullptr);
}

// ==========================================================================
// Flash attention on tensor cores (bf16x3 compensated).
// K and V both stored [key][d] bf16 hi/lo (pre-split by qkv epilogue).
// Q@K^T uses non-trans ldmatrix B (verified); P@V uses trans ldmatrix on V.
// ==========================================================================
#define FSTR   144
#define FT     (64 * FSTR)
#define F_KHI  0
#define F_KLO  FT
#define F_VHI  (2 * FT)
#define F_VLO  (3 * FT)
#define FSMEM  (4 * FT)

__global__ __launch_bounds__(256, 1)
void flash_tc_kernel()
{
    __shared__ __align__(128) char smem[FSMEM];
    const uint32_t sbase = smem_u32(smem);

    const int t  = threadIdx.x;
    const int l  = t & 31;
    const int w  = t >> 5;
    const int q0 = blockIdx.x * 128;
    const int h  = blockIdx.y;
    const int b  = blockIdx.z;

    const size_t headBase = ((size_t)b * NUM_HEADS + h) * SEQ * DK;
    const float*         Qg  = g_Q   + headBase;
    const __nv_bfloat16* Khi = g_Khi + headBase;
    const __nv_bfloat16* Klo = g_Klo + headBase;
    const __nv_bfloat16* Vhi = g_Vhi + headBase;
    const __nv_bfloat16* Vlo = g_Vlo + headBase;

    const float SCALE = 0.125f;

    // ---- stage Q (scaled) into smem, then ldmatrix into register frags ----
    {
        const int row  = t >> 1;
        const int half = (t & 1) * 32;
#pragma unroll
        for (int i = 0; i < 8; i++) {
            float4 q = *(const float4*)&Qg[(size_t)(q0 + row) * DK + half + 4 * i];
            q.x *= SCALE; q.y *= SCALE; q.z *= SCALE; q.w *= SCALE;
            const uint32_t o = (uint32_t)row * FSTR + (uint32_t)(half + 4 * i) * 2;
            cvt_split8b(q, smem + o, smem + 2 * FT + o);
        }
    }
    __syncthreads();

    uint32_t qh[4][4], ql[4][4];
    {
        const uint32_t aBase = sbase + (uint32_t)(w * 16 + (l & 15)) * FSTR
                             + (uint32_t)(l >> 4) * 16;
#pragma unroll
        for (int kt = 0; kt < 4; kt++) {
            ldsm4(qh[kt], aBase + kt * 32);
            ldsm4(ql[kt], aBase + 2 * FT + kt * 32);
        }
    }
    __syncthreads();

    float o_[8][4];
#pragma unroll
    for (int j = 0; j < 8; j++)
#pragma unroll
        for (int k = 0; k < 4; k++) o_[j][k] = 0.f;
    float m0 = -1e30f, m1 = -1e30f, l0 = 0.f, l1 = 0.f;

    // K-path ldsm base (rows l&15, 16B col half l>>4)
    const uint32_t lbase = sbase + (uint32_t)(l & 15) * FSTR + (uint32_t)(l >> 4) * 16;
    // V-path trans ldsm per-lane offset:
    //   row = ((l>>4)&1)*8 + (l&7) ; col half = ((l>>3)&1)*16B
    const uint32_t voff = (uint32_t)((((l >> 4) & 1) * 8 + (l & 7))) * FSTR
                        + (uint32_t)((l >> 3) & 1) * 16;

    for (int j0 = 0; j0 < SEQ; j0 += 64) {
        // ---- tile load: pure bf16 copies (no conversion) ----
        {
            const int key = t >> 2;
            const int gr  = (t & 3) * 16;        // byte granule within 128B row
            const char* kh = (const char*)(Khi + (size_t)(j0 + key) * DK);
            const char* kl = (const char*)(Klo + (size_t)(j0 + key) * DK);
            const char* vh = (const char*)(Vhi + (size_t)(j0 + key) * DK);
            const char* vl = (const char*)(Vlo + (size_t)(j0 + key) * DK);
            const uint32_t so = (uint32_t)key * FSTR;
#pragma unroll
            for (int p = 0; p < 2; p++) {
                const uint32_t cb = (uint32_t)gr + p * 64;
                *(uint4*)(smem + F_KHI + so + cb) = *(const uint4*)(kh + cb);
                *(uint4*)(smem + F_KLO + so + cb) = *(const uint4*)(kl + cb);
                *(uint4*)(smem + F_VHI + so + cb) = *(const uint4*)(vh + cb);
                *(uint4*)(smem + F_VLO + so + cb) = *(const uint4*)(vl + cb);
            }
        }
        __syncthreads();

        // ---- S = (Q*scale) @ K^T  (bf16x3) ----
        float s[8][4];
#pragma unroll
        for (int j = 0; j < 8; j++)
#pragma unroll
            for (int k = 0; k < 4; k++) s[j][k] = 0.f;

#pragma unroll
        for (int kt = 0; kt < 4; kt++) {
#pragma unroll
            for (int kg = 0; kg < 4; kg++) {
                uint32_t kh[4], kl[4];
                ldsm4(kh, lbase + F_KHI + kg * (16 * FSTR) + kt * 32);
                ldsm4(kl, lbase + F_KLO + kg * (16 * FSTR) + kt * 32);
#pragma unroll
                for (int ss = 0; ss < 2; ss++) {
                    float* sc = s[2 * kg + ss];
                    mma16816(sc, qh[kt], kh[ss], kh[ss + 2]);
                    mma16816(sc, qh[kt], kl[ss], kl[ss + 2]);
                    mma16816(sc, ql[kt], kh[ss], kh[ss + 2]);
                }
            }
        }

        // ---- online softmax ----
        {
            float mx0 = s[0][0], mx1 = s[0][2];
#pragma unroll
            for (int j = 0; j < 8; j++) {
                mx0 = fmaxf(mx0, fmaxf(s[j][0], s[j][1]));
                mx1 = fmaxf(mx1, fmaxf(s[j][2], s[j][3]));
            }
            mx0 = fmaxf(mx0, __shfl_xor_sync(0xffffffffu, mx0, 1));
            mx0 = fmaxf(mx0, __shfl_xor_sync(0xffffffffu, mx0, 2));
            mx1 = fmaxf(mx1, __shfl_xor_sync(0xffffffffu, mx1, 1));
            mx1 = fmaxf(mx1, __shfl_xor_sync(0xffffffffu, mx1, 2));

            const float mn0 = fmaxf(m0, mx0);
            const float mn1 = fmaxf(m1, mx1);
            const float c0 = __expf(m0 - mn0);
            const float c1 = __expf(m1 - mn1);
            m0 = mn0; m1 = mn1;

            float rs0 = 0.f, rs1 = 0.f;
#pragma unroll
            for (int j = 0; j < 8; j++) {
                s[j][0] = __expf(s[j][0] - mn0);
                s[j][1] = __expf(s[j][1] - mn0);
                s[j][2] = __expf(s[j][2] - mn1);
                s[j][3] = __expf(s[j][3] - mn1);
                rs0 += s[j][0] + s[j][1];
                rs1 += s[j][2] + s[j][3];
            }
            rs0 += __shfl_xor_sync(0xffffffffu, rs0, 1);
            rs0 += __shfl_xor_sync(0xffffffffu, rs0, 2);
            rs1 += __shfl_xor_sync(0xffffffffu, rs1, 1);
            rs1 += __shfl_xor_sync(0xffffffffu, rs1, 2);
            l0 = l0 * c0 + rs0;
            l1 = l1 * c1 + rs1;

#pragma unroll
            for (int j = 0; j < 8; j++) {
                o_[j][0] *= c0; o_[j][1] *= c0;
                o_[j][2] *= c1; o_[j][3] *= c1;
            }
        }

        // ---- O += P @ V  (bf16x3; V via trans ldmatrix on [key][d]) ----
#pragma unroll
        for (int kt = 0; kt < 4; kt++) {
            uint32_t phi[4], plo[4];
#pragma unroll
            for (int half = 0; half < 2; half++) {
                const float* sp = s[2 * kt + half];
#pragma unroll
                for (int rr = 0; rr < 2; rr++) {
                    const float x = sp[2 * rr + 0], y = sp[2 * rr + 1];
                    __nv_bfloat16 hx = __float2bfloat16(x);
                    __nv_bfloat16 hy = __float2bfloat16(y);
                    __nv_bfloat16 lx = __float2bfloat16(x - __bfloat162float(hx));
                    __nv_bfloat16 ly = __float2bfloat16(y - __bfloat162float(hy));
                    phi[2 * half + rr] = packbf(hx, hy);
                    plo[2 * half + rr] = packbf(lx, ly);
                }
            }
#pragma unroll
            for (int dg = 0; dg < 4; dg++) {
                uint32_t vh[4], vl[4];
                const uint32_t va = sbase + voff + kt * (16 * FSTR) + dg * 32;
                ldsm4t(vh, va + F_VHI);
                ldsm4t(vl, va + F_VLO);
#pragma unroll
                for (int ss = 0; ss < 2; ss++) {
                    float* oc = o_[2 * dg + ss];
                    mma16816(oc, phi, vh[ss], vh[ss + 2]);
                    mma16816(oc, phi, vl[ss], vl[ss + 2]);
                    mma16816(oc, plo, vh[ss], vh[ss + 2]);
                }
            }
        }
        __syncthreads();
    }

    // ---- epilogue: normalize, write merged-head fp32 [b*S, DMODEL] ----
    {
        const float inv0 = 1.f / l0;
        const float inv1 = 1.f / l1;
        const int r0 = q0 + w * 16 + (l >> 2);
        const int r1 = r0 + 8;
#pragma unroll
        for (int j = 0; j < 8; j++) {
            const int d = h * DK + j * 8 + (l & 3) * 2;
            *(float2*)&g_O[((size_t)b * SEQ + r0) * DMODEL + d] =
                make_float2(o_[j][0] * inv0, o_[j][1] * inv0);
            *(float2*)&g_O[((size_t)b * SEQ + r1) * DMODEL + d] =
                make_float2(o_[j][2] * inv1, o_[j][3] * inv1);
        }
    }
}

// ==========================================================================
// launch
// ==========================================================================
extern "C" void kernel_launch(void* const* d_in, const int* in_sizes, int n_in,
                              void* d_out, int out_size)
{
    (void)in_sizes; (void)n_in; (void)out_size;
    const float* Qin = (const float*)d_in[0];
    const float* Kin = (const float*)d_in[1];
    const float* Vin = (const float*)d_in[2];
    const float* Wq  = (const float*)d_in[3];
    const float* bq  = (const float*)d_in[4];
    const float* Wk  = (const float*)d_in[5];
    const float* bk  = (const float*)d_in[6];
    const float* Wv  = (const float*)d_in[7];
    const float* bv  = (const float*)d_in[8];
    const float* Wo  = (const float*)d_in[9];
    const float* bo  = (const float*)d_in[10];
    float* out = (float*)d_out;

    dim3 gProj(DMODEL / 128, MROWS / 128, 3);
    qkv_tc_kernel<<<gProj, 256>>>(Qin, Kin, Vin, Wq, bq, Wk, bk, Wv, bv);

    dim3 gAttn(SEQ / 128, NUM_HEADS, BATCH);
    flash_tc_kernel<<<gAttn, 256>>>();

    dim3 gOut(DMODEL / 128, MROWS / 128, 1);
    out_tc_kernel<<<gOut, 256>>>(Wo, bo, out);
}